// round 11
// baseline (speedup 1.0000x reference)
#include <cuda_runtime.h>
#include <cuda_bf16.h>
#include <math.h>

typedef unsigned long long ull;

// ---------------- sizes ----------------
#define BB   64
#define TT   512
#define NI   300
#define NH   512
#define G4   2048   // 4*NH
#define DA_  350
#define RR_  30
#define MLPH 2000
#define NCLS 5
#define MT   (BB*TT)      // 32768 rows (t*64+b)
#define KMLP (RR_*2*NH)   // 30720
#define NZSPLIT 16

// ---------------- scratch (__device__ globals; no allocation allowed) ----------------
__device__ float d_X   [(size_t)TT*BB*NI];        // [t][b][300]
__device__ float d_XGf [(size_t)TT*BB*G4];        // [t][b][2048]
__device__ float d_XGb [(size_t)TT*BB*G4];
__device__ float d_HBUF[2*2*BB*NH];               // [dir][phase][b][512]
__device__ float d_CBUF[2*NH*BB];                 // [dir][unit][b]
__device__ float d_HOUT[(size_t)BB*TT*2*NH];      // [b][t][1024]
__device__ float d_S1  [(size_t)MT*DA_];
__device__ float d_S2  [(size_t)MT*RR_];
__device__ float d_A   [(size_t)BB*RR_*TT];       // [b][r][t]
__device__ float d_M   [(size_t)BB*RR_*2*NH];     // [b][r][1024] == BM [64][30720]
__device__ float d_SPL [(size_t)NZSPLIT*BB*MLPH];
__device__ float d_RELU[(size_t)BB*MLPH];
__device__ float d_penal;

// ---------------- f32x2 helpers ----------------
__device__ __forceinline__ ull pk2(float x){
    ull r; asm("mov.b64 %0, {%1, %1};" : "=l"(r) : "f"(x)); return r;
}
__device__ __forceinline__ ull pk(float x, float y){
    ull r; asm("mov.b64 %0, {%1, %2};" : "=l"(r) : "f"(x), "f"(y)); return r;
}
__device__ __forceinline__ ull fma2(ull a, ull b, ull c){
    ull d; asm("fma.rn.f32x2 %0, %1, %2, %3;" : "=l"(d) : "l"(a), "l"(b), "l"(c)); return d;
}
__device__ __forceinline__ float2 upk(ull v){
    float2 f; asm("mov.b64 {%0, %1}, %2;" : "=f"(f.x), "=f"(f.y) : "l"(v)); return f;
}
__device__ __forceinline__ float sigm(float x){ return 1.f/(1.f+__expf(-x)); }

// ---------------- init ----------------
__global__ void init_zero(){
    int idx = blockIdx.x*256 + threadIdx.x;
    if (idx < 2*2*BB*NH) d_HBUF[idx] = 0.f;
    if (idx < 2*NH*BB)   d_CBUF[idx] = 0.f;
    if (idx == 0)        d_penal = 0.f;
}

// ---------------- embedding + mask ----------------
__global__ void embed_kernel(const int* __restrict__ ids, const int* __restrict__ len,
                             const float* __restrict__ emb){
    int bid = blockIdx.x;          // = t*64 + b
    int t = bid >> 6, b = bid & 63;
    int tid = threadIdx.x;
    if (tid >= 75) return;         // 300 floats = 75 float4
    float4 v;
    if (t < len[b]) {
        int id = ids[b*TT + t];
        v = ((const float4*)(emb + (size_t)id*NI))[tid];
    } else v = make_float4(0.f,0.f,0.f,0.f);
    ((float4*)(d_X + (size_t)bid*NI))[tid] = v;
}

// ---------------- generic SGEMM: C[m][n] = dot(A[m,:K], B[n,:K]) ----------------
// BM=64, BN=128, BK=32, 256 threads, 4x8 thread tile via f32x2.
// epi: 0 = plain, 1 = tanh. Split-K along gridDim.z into slabs of kSplitLen.
__global__ void sgemm_tn(const float* __restrict__ A, const float* __restrict__ Bw,
                         float* __restrict__ C, int M, int N, int K,
                         int kSplitLen, int epi){
    __shared__ __align__(16) float As[32][68];
    __shared__ __align__(16) float Bs[32][132];
    int mBase = blockIdx.y * 64;
    int nBase = blockIdx.x * 128;
    int k0 = blockIdx.z * kSplitLen;
    int k1 = min(K, k0 + kSplitLen);
    float* Cz = C + (size_t)blockIdx.z * M * N;
    int tid = threadIdx.x;
    int tm = (tid >> 4) << 2;   // 0..60
    int tn = (tid & 15) << 3;   // 0..120
    ull acc[4][4];
    #pragma unroll
    for (int i=0;i<4;i++)
        #pragma unroll
        for (int j=0;j<4;j++) acc[i][j] = 0ULL;

    int kkA = tid & 31, rA = (tid >> 5) << 3;   // 8 rows / thread
    int kkB = tid & 31, rB = (tid >> 5) << 4;   // 16 rows / thread

    for (int kc = k0; kc < k1; kc += 32){
        #pragma unroll
        for (int i=0;i<8;i++){
            int m = mBase + rA + i; int k = kc + kkA;
            As[kkA][rA+i] = (m < M && k < k1) ? A[(size_t)m*K + k] : 0.f;
        }
        #pragma unroll
        for (int i=0;i<16;i++){
            int n = nBase + rB + i; int k = kc + kkB;
            Bs[kkB][rB+i] = (n < N && k < k1) ? Bw[(size_t)n*K + k] : 0.f;
        }
        __syncthreads();
        #pragma unroll
        for (int k=0;k<32;k++){
            float4 a4 = *reinterpret_cast<const float4*>(&As[k][tm]);
            ulonglong2 q0 = *reinterpret_cast<const ulonglong2*>(&Bs[k][tn]);
            ulonglong2 q1 = *reinterpret_cast<const ulonglong2*>(&Bs[k][tn+4]);
            ull ap0 = pk2(a4.x), ap1 = pk2(a4.y), ap2 = pk2(a4.z), ap3 = pk2(a4.w);
            acc[0][0]=fma2(ap0,q0.x,acc[0][0]); acc[0][1]=fma2(ap0,q0.y,acc[0][1]);
            acc[0][2]=fma2(ap0,q1.x,acc[0][2]); acc[0][3]=fma2(ap0,q1.y,acc[0][3]);
            acc[1][0]=fma2(ap1,q0.x,acc[1][0]); acc[1][1]=fma2(ap1,q0.y,acc[1][1]);
            acc[1][2]=fma2(ap1,q1.x,acc[1][2]); acc[1][3]=fma2(ap1,q1.y,acc[1][3]);
            acc[2][0]=fma2(ap2,q0.x,acc[2][0]); acc[2][1]=fma2(ap2,q0.y,acc[2][1]);
            acc[2][2]=fma2(ap2,q1.x,acc[2][2]); acc[2][3]=fma2(ap2,q1.y,acc[2][3]);
            acc[3][0]=fma2(ap3,q0.x,acc[3][0]); acc[3][1]=fma2(ap3,q0.y,acc[3][1]);
            acc[3][2]=fma2(ap3,q1.x,acc[3][2]); acc[3][3]=fma2(ap3,q1.y,acc[3][3]);
        }
        __syncthreads();
    }
    #pragma unroll
    for (int i=0;i<4;i++){
        int m = mBase + tm + i;
        if (m >= M) continue;
        #pragma unroll
        for (int j=0;j<4;j++){
            float2 f2 = upk(acc[i][j]);
            int n = nBase + tn + 2*j;
            if (n < N){
                float v = f2.x; if (epi==1) v = tanhf(v);
                Cz[(size_t)m*N + n] = v;
            }
            if (n+1 < N){
                float v = f2.y; if (epi==1) v = tanhf(v);
                Cz[(size_t)m*N + n + 1] = v;
            }
        }
    }
}

// ---------------- one LSTM time-step (both directions; 128 blocks) ----------------
// block: dir = bx>>6, 8 hidden units (all 4 gates), all 64 batches.
__global__ void lstm_step(const int* __restrict__ len,
                          const float* __restrict__ Whh_f,
                          const float* __restrict__ Whh_b,
                          int t){
    __shared__ __align__(16) float hs[64][68];   // [k][b]
    __shared__ __align__(16) float ws[32][65];   // [gate-row][k]
    __shared__ __align__(16) float sg[32][65];   // gate preacts [gate-row][b]
    int tid = threadIdx.x;
    int d  = blockIdx.x >> 6;
    int bu = blockIdx.x & 63;
    int u0 = bu << 3;
    const float* W = d ? Whh_b : Whh_f;
    const float* Hin  = d_HBUF + (size_t)(d*2 + (t & 1)) * (BB*NH);
    float*       Hnxt = d_HBUF + (size_t)(d*2 + ((t+1) & 1)) * (BB*NH);
    const float* XGd = d ? d_XGb : d_XGf;

    int r  = tid >> 3;            // 0..31 gate-row within block (gate*8 + unit)
    int b0 = (tid & 7) << 3;      // batch base (8 batches / thread)
    ull acc[4] = {0ULL,0ULL,0ULL,0ULL};
    int gR = r >> 3, uR = r & 7;
    int row_r = (gR << 9) + u0 + uR;   // global gate row in [0,2048)

    int kkH = tid & 63, bH = tid >> 6;   // h loader
    int kkW = tid & 63, rqW = tid >> 6;  // w loader

    for (int kc = 0; kc < NH; kc += 64){
        #pragma unroll
        for (int i=0;i<16;i++){
            int b = (bH<<4) + i;
            hs[kkH][b] = Hin[b*NH + kc + kkH];
        }
        #pragma unroll
        for (int i=0;i<8;i++){
            int rr = (rqW<<3) + i;
            int row = ((rr>>3)<<9) + u0 + (rr&7);
            ws[rr][kkW] = W[(size_t)row*NH + kc + kkW];
        }
        __syncthreads();
        #pragma unroll
        for (int k=0;k<64;k++){
            ull w2 = pk2(ws[r][k]);
            ulonglong2 h01 = *reinterpret_cast<const ulonglong2*>(&hs[k][b0]);
            ulonglong2 h23 = *reinterpret_cast<const ulonglong2*>(&hs[k][b0+4]);
            acc[0] = fma2(w2, h01.x, acc[0]);
            acc[1] = fma2(w2, h01.y, acc[1]);
            acc[2] = fma2(w2, h23.x, acc[2]);
            acc[3] = fma2(w2, h23.y, acc[3]);
        }
        __syncthreads();
    }
    // add xg and publish gate preactivations
    #pragma unroll
    for (int j=0;j<4;j++){
        float2 f2 = upk(acc[j]);
        int b = b0 + 2*j;
        {
            int L = len[b];
            int tsrc = (d && t < L) ? (L-1-t) : t;
            sg[r][b] = f2.x + XGd[((size_t)tsrc*BB + b)*G4 + row_r];
        }
        {
            int bb = b+1;
            int L = len[bb];
            int tsrc = (d && t < L) ? (L-1-t) : t;
            sg[r][bb] = f2.y + XGd[((size_t)tsrc*BB + bb)*G4 + row_r];
        }
    }
    __syncthreads();
    // cell update: 512 (uu,b) pairs, 2 per thread
    #pragma unroll
    for (int e=0;e<2;e++){
        int p  = tid*2 + e;
        int uu = p >> 6;
        int b  = p & 63;
        float gi = sg[uu][b];
        float gf = sg[8+uu][b];
        float gg = sg[16+uu][b];
        float go = sg[24+uu][b];
        int cu = u0 + uu;
        size_t cidx = (size_t)d*NH*BB + (size_t)cu*BB + b;
        float c = d_CBUF[cidx];
        c = sigm(gf)*c + sigm(gi)*tanhf(gg);
        float h = sigm(go)*tanhf(c);
        d_CBUF[cidx] = c;
        Hnxt[b*NH + cu] = h;
        int L = len[b];
        int tdst = (t < L) ? (d ? (L-1-t) : t) : t;
        d_HOUT[((size_t)b*TT + tdst)*(2*NH) + d*NH + cu] = h;
    }
}

// ---------------- masked softmax over T per (b,r) ----------------
__global__ void softmax_kernel(const int* __restrict__ len){
    int b = blockIdx.x / RR_, rr = blockIdx.x % RR_;
    int L = len[b];
    int tid = threadIdx.x;
    int t1 = tid + 256;
    float v0 = (tid < L) ? d_S2[((size_t)b*TT + tid)*RR_ + rr] : -1e30f;
    float v1 = (t1  < L) ? d_S2[((size_t)b*TT + t1 )*RR_ + rr] : -1e30f;
    __shared__ float red[256];
    red[tid] = fmaxf(v0, v1);
    __syncthreads();
    for (int s=128; s>0; s>>=1){ if (tid<s) red[tid] = fmaxf(red[tid], red[tid+s]); __syncthreads(); }
    float vmax = red[0];
    __syncthreads();
    float e0 = (tid < L) ? __expf(v0 - vmax) : 0.f;
    float e1 = (t1  < L) ? __expf(v1 - vmax) : 0.f;
    red[tid] = e0 + e1;
    __syncthreads();
    for (int s=128; s>0; s>>=1){ if (tid<s) red[tid] += red[tid+s]; __syncthreads(); }
    float inv = 1.f / red[0];
    size_t base = ((size_t)b*RR_ + rr)*TT;
    d_A[base + tid] = e0 * inv;
    d_A[base + t1 ] = e1 * inv;
}

// ---------------- M = A @ Hout  (2 h-values per thread, f32x2) ----------------
__global__ void mpool_kernel(){
    int b = blockIdx.y;
    int h = (blockIdx.x*256 + threadIdx.x)*2;  // even h in [0,1024)
    __shared__ __align__(16) float sa[RR_][66];
    ull acc[RR_];
    #pragma unroll
    for (int rr=0; rr<RR_; rr++) acc[rr] = 0ULL;
    for (int tc=0; tc<TT; tc+=64){
        for (int i = threadIdx.x; i < RR_*64; i += 256){
            int rr = i >> 6, tt = i & 63;
            sa[rr][tt] = d_A[((size_t)b*RR_ + rr)*TT + tc + tt];
        }
        __syncthreads();
        for (int tt=0; tt<64; tt++){
            float2 hv = *reinterpret_cast<const float2*>(
                &d_HOUT[((size_t)b*TT + tc + tt)*(2*NH) + h]);
            ull hv2 = pk(hv.x, hv.y);
            #pragma unroll
            for (int rr=0; rr<RR_; rr++)
                acc[rr] = fma2(pk2(sa[rr][tt]), hv2, acc[rr]);
        }
        __syncthreads();
    }
    #pragma unroll
    for (int rr=0; rr<RR_; rr++){
        float2 f2 = upk(acc[rr]);
        *reinterpret_cast<float2*>(&d_M[((size_t)b*RR_ + rr)*(2*NH) + h]) = f2;
    }
}

// ---------------- penalization ||AA^T - I||_F^2 ----------------
__global__ void aat_kernel(){
    int b = blockIdx.x, tid = threadIdx.x;
    float loc = 0.f;
    for (int p = tid; p < RR_*RR_; p += 256){
        int r = p / RR_, s = p % RR_;
        const float4* Ar = (const float4*)(d_A + ((size_t)b*RR_ + r)*TT);
        const float4* As = (const float4*)(d_A + ((size_t)b*RR_ + s)*TT);
        float dot = 0.f;
        for (int k=0; k<TT/4; k++){
            float4 x = Ar[k], y = As[k];
            dot += x.x*y.x + x.y*y.y + x.z*y.z + x.w*y.w;
        }
        float dd = dot - (r==s ? 1.f : 0.f);
        loc += dd*dd;
    }
    __shared__ float red[256];
    red[tid] = loc;
    __syncthreads();
    for (int s=128; s>0; s>>=1){ if (tid<s) red[tid] += red[tid+s]; __syncthreads(); }
    if (tid == 0) atomicAdd(&d_penal, red[0]);
}

// ---------------- split-K reduce + bias + relu ----------------
__global__ void rbias_relu(const float* __restrict__ bm){
    int idx = blockIdx.x*256 + threadIdx.x;
    if (idx >= BB*MLPH) return;
    int n = idx % MLPH;
    float s = 0.f;
    #pragma unroll
    for (int z=0; z<NZSPLIT; z++) s += d_SPL[(size_t)z*BB*MLPH + idx];
    d_RELU[idx] = fmaxf(s + bm[n], 0.f);
}

// ---------------- final decode + penal write ----------------
__global__ void decode_kernel(const float* __restrict__ Wd, const float* __restrict__ bd,
                              float* __restrict__ out, int out_size){
    int b = blockIdx.x, tid = threadIdx.x;
    float p[NCLS] = {0.f,0.f,0.f,0.f,0.f};
    for (int k = tid; k < MLPH; k += 256){
        float v = d_RELU[(size_t)b*MLPH + k];
        #pragma unroll
        for (int c=0; c<NCLS; c++) p[c] += v * Wd[(size_t)c*MLPH + k];
    }
    __shared__ float red[256];
    for (int c=0; c<NCLS; c++){
        red[tid] = p[c];
        __syncthreads();
        for (int s=128; s>0; s>>=1){ if (tid<s) red[tid] += red[tid+s]; __syncthreads(); }
        if (tid == 0) out[b*NCLS + c] = red[0] + bd[c];
        __syncthreads();
    }
    if (b == 0 && tid == 0 && out_size > BB*NCLS)
        out[BB*NCLS] = d_penal * (1.f/BB);
}

// ---------------- launch ----------------
extern "C" void kernel_launch(void* const* d_in, const int* in_sizes, int n_in,
                              void* d_out, int out_size){
    const int*   ids  = (const int*)  d_in[0];
    const int*   len  = (const int*)  d_in[1];
    const float* emb  = (const float*)d_in[2];
    const float* Wihf = (const float*)d_in[3];
    const float* Whhf = (const float*)d_in[4];
    const float* Wihb = (const float*)d_in[5];
    const float* Whhb = (const float*)d_in[6];
    const float* W1   = (const float*)d_in[7];
    const float* W2   = (const float*)d_in[8];
    const float* Wm   = (const float*)d_in[9];
    const float* bm   = (const float*)d_in[10];
    const float* Wd   = (const float*)d_in[11];
    const float* bd   = (const float*)d_in[12];
    float* out = (float*)d_out;

    void *pX, *pXGf, *pXGb, *pHOUT, *pS1, *pS2, *pM, *pSPL;
    cudaGetSymbolAddress(&pX,    d_X);
    cudaGetSymbolAddress(&pXGf,  d_XGf);
    cudaGetSymbolAddress(&pXGb,  d_XGb);
    cudaGetSymbolAddress(&pHOUT, d_HOUT);
    cudaGetSymbolAddress(&pS1,   d_S1);
    cudaGetSymbolAddress(&pS2,   d_S2);
    cudaGetSymbolAddress(&pM,    d_M);
    cudaGetSymbolAddress(&pSPL,  d_SPL);

    init_zero<<<512,256>>>();
    embed_kernel<<<MT,128>>>(ids, len, emb);

    // xg = X @ W_ih^T for both directions
    dim3 gXG(G4/128, MT/64, 1);
    sgemm_tn<<<gXG,256>>>((const float*)pX, Wihf, (float*)pXGf, MT, G4, NI, NI, 0);
    sgemm_tn<<<gXG,256>>>((const float*)pX, Wihb, (float*)pXGb, MT, G4, NI, NI, 0);

    // recurrence: 512 sequential steps, both directions per step
    for (int t=0; t<TT; t++)
        lstm_step<<<128,256>>>(len, Whhf, Whhb, t);

    // attention scores
    dim3 gS1((DA_+127)/128, MT/64, 1);
    sgemm_tn<<<gS1,256>>>((const float*)pHOUT, W1, (float*)pS1, MT, DA_, 2*NH, 2*NH, 1);
    dim3 gS2(1, MT/64, 1);
    sgemm_tn<<<gS2,256>>>((const float*)pS1, W2, (float*)pS2, MT, RR_, DA_, DA_, 0);

    softmax_kernel<<<BB*RR_,256>>>(len);
    mpool_kernel<<<dim3(2,BB),256>>>();
    aat_kernel<<<BB,256>>>();

    // MLP: split-K GEMM + reduce/bias/relu
    dim3 gM((MLPH+127)/128, 1, NZSPLIT);
    sgemm_tn<<<gM,256>>>((const float*)pM, Wm, (float*)pSPL, BB, MLPH, KMLP, KMLP/NZSPLIT, 0);
    rbias_relu<<<(BB*MLPH+255)/256,256>>>(bm);

    decode_kernel<<<BB,256>>>(Wd, bd, out, out_size);
}

// round 13
// speedup vs baseline: 1.5825x; 1.5825x over previous
#include <cuda_runtime.h>
#include <cuda_bf16.h>
#include <math.h>

typedef unsigned long long ull;

// ---------------- sizes ----------------
#define BB   64
#define TT   512
#define NI   300
#define NH   512
#define G4   2048   // 4*NH
#define DA_  350
#define RR_  30
#define MLPH 2000
#define NCLS 5
#define MT   (BB*TT)      // 32768 rows (m = t*64+b)
#define KMLP (RR_*2*NH)   // 30720
#define NZSPLIT 16
#define WSTR 516          // padded W row stride in smem (floats)

// ---------------- scratch ----------------
__device__ float d_X   [(size_t)TT*BB*NI];        // [t][b][300]  (m = t*64+b)
__device__ float d_XGf [(size_t)TT*G4*BB];        // [t][gate_row][b]  (transposed!)
__device__ float d_XGb [(size_t)TT*G4*BB];
__device__ float d_HBUF[2*2*BB*NH];               // [dir][phase][b][512]
__device__ float d_HOUT[(size_t)TT*BB*2*NH];      // [t][b][1024]  (m = t*64+b)
__device__ float d_S1  [(size_t)MT*DA_];
__device__ float d_S2  [(size_t)MT*RR_];
__device__ float d_A   [(size_t)BB*RR_*TT];       // [b][r][t]
__device__ float d_M   [(size_t)BB*RR_*2*NH];     // [b][r][1024] == BM [64][30720]
__device__ float d_SPL [(size_t)NZSPLIT*BB*MLPH];
__device__ float d_RELU[(size_t)BB*MLPH];
__device__ float d_penal;
__device__ unsigned d_bar;

// ---------------- f32x2 helpers ----------------
__device__ __forceinline__ ull pk2(float x){
    ull r; asm("mov.b64 %0, {%1, %1};" : "=l"(r) : "f"(x)); return r;
}
__device__ __forceinline__ ull pk(float x, float y){
    ull r; asm("mov.b64 %0, {%1, %2};" : "=l"(r) : "f"(x), "f"(y)); return r;
}
__device__ __forceinline__ ull fma2(ull a, ull b, ull c){
    ull d; asm("fma.rn.f32x2 %0, %1, %2, %3;" : "=l"(d) : "l"(a), "l"(b), "l"(c)); return d;
}
__device__ __forceinline__ float2 upk(ull v){
    float2 f; asm("mov.b64 {%0, %1}, %2;" : "=f"(f.x), "=f"(f.y) : "l"(v)); return f;
}
__device__ __forceinline__ float sigm(float x){ return 1.f/(1.f+__expf(-x)); }

// ---------------- init ----------------
__global__ void init_zero(){
    int idx = blockIdx.x*256 + threadIdx.x;
    if (idx < 2*2*BB*NH) d_HBUF[idx] = 0.f;
    if (idx == 0){ d_penal = 0.f; d_bar = 0u; }
}

// ---------------- embedding + mask ----------------
__global__ void embed_kernel(const int* __restrict__ ids, const int* __restrict__ len,
                             const float* __restrict__ emb){
    int bid = blockIdx.x;          // = t*64 + b
    int t = bid >> 6, b = bid & 63;
    int tid = threadIdx.x;
    if (tid >= 75) return;         // 300 floats = 75 float4
    float4 v;
    if (t < len[b]) {
        int id = ids[b*TT + t];
        v = ((const float4*)(emb + (size_t)id*NI))[tid];
    } else v = make_float4(0.f,0.f,0.f,0.f);
    ((float4*)(d_X + (size_t)bid*NI))[tid] = v;
}

// ---------------- generic SGEMM: C[m][n] = dot(A[m,:K], B[n,:K]) ----------------
// BM=64, BN=128, BK=32, 256 threads, 4x8 thread tile via f32x2.
// epi: 0 = plain, 1 = tanh, 2 = transposed store C^T per 64-row block:
//      Cz[((m>>6)*N + n)*64 + (m&63)]   (requires full tiles: M%64==0, N%128==0)
__global__ void sgemm_tn(const float* __restrict__ A, const float* __restrict__ Bw,
                         float* __restrict__ C, int M, int N, int K,
                         int kSplitLen, int epi){
    __shared__ __align__(16) float smbuf[32*68 + 32*132];
    float* smA = smbuf;             // [32][68]
    float* smB = smbuf + 32*68;     // [32][132]
    int mBase = blockIdx.y * 64;
    int nBase = blockIdx.x * 128;
    int k0 = blockIdx.z * kSplitLen;
    int k1 = min(K, k0 + kSplitLen);
    float* Cz = C + (size_t)blockIdx.z * M * N;
    int tid = threadIdx.x;
    int tm = (tid >> 4) << 2;   // 0..60
    int tn = (tid & 15) << 3;   // 0..120
    ull acc[4][4];
    #pragma unroll
    for (int i=0;i<4;i++)
        #pragma unroll
        for (int j=0;j<4;j++) acc[i][j] = 0ULL;

    int kkA = tid & 31, rA = (tid >> 5) << 3;   // 8 rows / thread
    int kkB = tid & 31, rB = (tid >> 5) << 4;   // 16 rows / thread

    for (int kc = k0; kc < k1; kc += 32){
        #pragma unroll
        for (int i=0;i<8;i++){
            int m = mBase + rA + i; int k = kc + kkA;
            smA[kkA*68 + rA+i] = (m < M && k < k1) ? A[(size_t)m*K + k] : 0.f;
        }
        #pragma unroll
        for (int i=0;i<16;i++){
            int n = nBase + rB + i; int k = kc + kkB;
            smB[kkB*132 + rB+i] = (n < N && k < k1) ? Bw[(size_t)n*K + k] : 0.f;
        }
        __syncthreads();
        #pragma unroll
        for (int k=0;k<32;k++){
            float4 a4 = *reinterpret_cast<const float4*>(&smA[k*68 + tm]);
            ulonglong2 q0 = *reinterpret_cast<const ulonglong2*>(&smB[k*132 + tn]);
            ulonglong2 q1 = *reinterpret_cast<const ulonglong2*>(&smB[k*132 + tn+4]);
            ull ap0 = pk2(a4.x), ap1 = pk2(a4.y), ap2 = pk2(a4.z), ap3 = pk2(a4.w);
            acc[0][0]=fma2(ap0,q0.x,acc[0][0]); acc[0][1]=fma2(ap0,q0.y,acc[0][1]);
            acc[0][2]=fma2(ap0,q1.x,acc[0][2]); acc[0][3]=fma2(ap0,q1.y,acc[0][3]);
            acc[1][0]=fma2(ap1,q0.x,acc[1][0]); acc[1][1]=fma2(ap1,q0.y,acc[1][1]);
            acc[1][2]=fma2(ap1,q1.x,acc[1][2]); acc[1][3]=fma2(ap1,q1.y,acc[1][3]);
            acc[2][0]=fma2(ap2,q0.x,acc[2][0]); acc[2][1]=fma2(ap2,q0.y,acc[2][1]);
            acc[2][2]=fma2(ap2,q1.x,acc[2][2]); acc[2][3]=fma2(ap2,q1.y,acc[2][3]);
            acc[3][0]=fma2(ap3,q0.x,acc[3][0]); acc[3][1]=fma2(ap3,q0.y,acc[3][1]);
            acc[3][2]=fma2(ap3,q1.x,acc[3][2]); acc[3][3]=fma2(ap3,q1.y,acc[3][3]);
        }
        __syncthreads();
    }

    if (epi == 2){
        // transposed store via smem stage: Cs[n_local][m_local], stride 65
        float* Cs = smbuf;  // 64*65 = 4160 floats <= 6400 available
        int myHalf = (tn >= 64) ? 1 : 0;
        #pragma unroll
        for (int half=0; half<2; half++){
            __syncthreads();
            if (half == myHalf){
                #pragma unroll
                for (int i=0;i<4;i++)
                    #pragma unroll
                    for (int j=0;j<4;j++){
                        float2 f2 = upk(acc[i][j]);
                        int nl = tn + 2*j - half*64;
                        Cs[nl*65 + tm+i]     = f2.x;
                        Cs[(nl+1)*65 + tm+i] = f2.y;
                    }
            }
            __syncthreads();
            int row = tid >> 2, part = tid & 3;   // row 0..63, 16 floats per part
            size_t gbase = ((size_t)(mBase >> 6) * N + (nBase + half*64 + row)) * 64 + part*16;
            #pragma unroll
            for (int w=0; w<4; w++){
                float4 v;
                v.x = Cs[row*65 + part*16 + w*4 + 0];
                v.y = Cs[row*65 + part*16 + w*4 + 1];
                v.z = Cs[row*65 + part*16 + w*4 + 2];
                v.w = Cs[row*65 + part*16 + w*4 + 3];
                *reinterpret_cast<float4*>(Cz + gbase + w*4) = v;
            }
        }
        return;
    }

    #pragma unroll
    for (int i=0;i<4;i++){
        int m = mBase + tm + i;
        if (m >= M) continue;
        #pragma unroll
        for (int j=0;j<4;j++){
            float2 f2 = upk(acc[i][j]);
            int n = nBase + tn + 2*j;
            if (n < N){
                float v = f2.x; if (epi==1) v = tanhf(v);
                Cz[(size_t)m*N + n] = v;
            }
            if (n+1 < N){
                float v = f2.y; if (epi==1) v = tanhf(v);
                Cz[(size_t)m*N + n + 1] = v;
            }
        }
    }
}

// ---------------- persistent bidirectional LSTM (one launch, 512 steps) ----------------
// 128 blocks (all co-resident): dir = bid>>6, 8 hidden units (32 gate rows) each.
// W_hh rows live in smem for the whole kernel; c in registers; h exchanged via
// global double-buffer + software grid barrier.
__global__ void __launch_bounds__(256,1)
lstm_persist(const int* __restrict__ len,
             const float* __restrict__ Whhf,
             const float* __restrict__ Whhb){
    extern __shared__ __align__(16) float sm[];
    float* ws = sm;                    // [32][WSTR]
    float* hs = sm + 32*WSTR;          // [64][68]  (k-local, b)
    float* sg = hs + 64*68;            // [32][65], reused as sh[b][8]

    int tid = threadIdx.x;
    int d  = blockIdx.x >> 6;
    int u0 = (blockIdx.x & 63) << 3;
    const float* W   = d ? Whhb : Whhf;
    const float* XGd = d ? d_XGb : d_XGf;   // [t][gate_row][b]

    // load my 32 gate rows of W into smem (once)
    for (int idx = tid; idx < 32*NH; idx += 256){
        int rr = idx >> 9, k = idx & 511;
        int row = ((rr>>3)<<9) + u0 + (rr&7);
        ws[rr*WSTR + k] = W[(size_t)row*NH + k];
    }

    int r  = tid >> 3;                 // gate-row 0..31 (gate*8+unit)
    int b0 = (tid & 7) << 3;
    int gR = r >> 3, uR = r & 7;
    int row_r = (gR << 9) + u0 + uR;
    // conflict-free granule swap: b0>=32 reads upper granule first
    int bo = (b0 >= 32) ? 4 : 0;
    int bL = b0 + bo;
    int bH = b0 + (4 - bo);
    int bj0 = bL, bj1 = bL+2, bj2 = bH, bj3 = bH+2;
    int l_j0a = len[bj0], l_j0b = len[bj0+1];
    int l_j1a = len[bj1], l_j1b = len[bj1+1];
    int l_j2a = len[bj2], l_j2b = len[bj2+1];
    int l_j3a = len[bj3], l_j3b = len[bj3+1];

    // cell state: 2 cells per thread
    int p0 = tid*2;
    int uu = p0 >> 6, bA = p0 & 63;    // cells (uu,bA), (uu,bA+1)
    float c0 = 0.f, c1 = 0.f;
    int lw = (tid < 64) ? len[tid] : 0;

    int kk = tid & 63, bbase = (tid >> 6) << 4;   // hs chunk loader
    __syncthreads();

    float* HB = d_HBUF + (size_t)d*2*(BB*NH);

    for (int t = 0; t < TT; t++){
        const float* Hin = HB + (size_t)(t & 1)*(BB*NH);
        float*      Hnxt = HB + (size_t)((t+1) & 1)*(BB*NH);
        ull a0=0ULL, a1=0ULL, a2=0ULL, a3=0ULL;

        for (int kc = 0; kc < NH; kc += 64){
            // fill hs[k][b]: coalesced ldcg, conflict-free STS.128
            float rbuf[16];
            #pragma unroll
            for (int i=0;i<16;i++)
                rbuf[i] = __ldcg(&Hin[(bbase+i)*NH + kc + kk]);
            #pragma unroll
            for (int q=0;q<4;q++){
                float4 v = make_float4(rbuf[4*q], rbuf[4*q+1], rbuf[4*q+2], rbuf[4*q+3]);
                *reinterpret_cast<float4*>(&hs[kk*68 + bbase + 4*q]) = v;
            }
            __syncthreads();
            #pragma unroll
            for (int k=0;k<64;k++){
                ull w2 = pk2(ws[r*WSTR + kc + k]);
                ulonglong2 hA = *reinterpret_cast<const ulonglong2*>(&hs[k*68 + bL]);
                ulonglong2 hB = *reinterpret_cast<const ulonglong2*>(&hs[k*68 + bH]);
                a0 = fma2(w2, hA.x, a0);
                a1 = fma2(w2, hA.y, a1);
                a2 = fma2(w2, hB.x, a2);
                a3 = fma2(w2, hB.y, a3);
            }
            __syncthreads();
        }

        // add xg (coalesced-in-b layout) and publish gate preacts
        {
            float2 f;
            f = upk(a0);
            { int L=l_j0a; int ts=(d && t<L)?(L-1-t):t; sg[r*65+bj0]   = f.x + XGd[((size_t)ts*G4+row_r)*64 + bj0]; }
            { int L=l_j0b; int ts=(d && t<L)?(L-1-t):t; sg[r*65+bj0+1] = f.y + XGd[((size_t)ts*G4+row_r)*64 + bj0+1]; }
            f = upk(a1);
            { int L=l_j1a; int ts=(d && t<L)?(L-1-t):t; sg[r*65+bj1]   = f.x + XGd[((size_t)ts*G4+row_r)*64 + bj1]; }
            { int L=l_j1b; int ts=(d && t<L)?(L-1-t):t; sg[r*65+bj1+1] = f.y + XGd[((size_t)ts*G4+row_r)*64 + bj1+1]; }
            f = upk(a2);
            { int L=l_j2a; int ts=(d && t<L)?(L-1-t):t; sg[r*65+bj2]   = f.x + XGd[((size_t)ts*G4+row_r)*64 + bj2]; }
            { int L=l_j2b; int ts=(d && t<L)?(L-1-t):t; sg[r*65+bj2+1] = f.y + XGd[((size_t)ts*G4+row_r)*64 + bj2+1]; }
            f = upk(a3);
            { int L=l_j3a; int ts=(d && t<L)?(L-1-t):t; sg[r*65+bj3]   = f.x + XGd[((size_t)ts*G4+row_r)*64 + bj3]; }
            { int L=l_j3b; int ts=(d && t<L)?(L-1-t):t; sg[r*65+bj3+1] = f.y + XGd[((size_t)ts*G4+row_r)*64 + bj3+1]; }
        }
        __syncthreads();

        // cell update (2 cells in registers)
        float h0, h1;
        {
            float gi = sg[uu*65 + bA],      gf = sg[(8+uu)*65 + bA];
            float gg = sg[(16+uu)*65 + bA], go = sg[(24+uu)*65 + bA];
            c0 = sigm(gf)*c0 + sigm(gi)*tanhf(gg);
            h0 = sigm(go)*tanhf(c0);
        }
        {
            float gi = sg[uu*65 + bA+1],      gf = sg[(8+uu)*65 + bA+1];
            float gg = sg[(16+uu)*65 + bA+1], go = sg[(24+uu)*65 + bA+1];
            c1 = sigm(gf)*c1 + sigm(gi)*tanhf(gg);
            h1 = sigm(go)*tanhf(c1);
        }
        __syncthreads();                  // done reading sg; reuse as sh[b][8]
        sg[bA*8 + uu]     = h0;
        sg[(bA+1)*8 + uu] = h1;
        __syncthreads();

        if (tid < 64){
            int b = tid;
            float4 v0 = *reinterpret_cast<const float4*>(&sg[b*8]);
            float4 v1 = *reinterpret_cast<const float4*>(&sg[b*8+4]);
            *reinterpret_cast<float4*>(&Hnxt[b*NH + u0])     = v0;
            *reinterpret_cast<float4*>(&Hnxt[b*NH + u0 + 4]) = v1;
            int tdst = (t < lw) ? (d ? (lw-1-t) : t) : t;
            float* ho = &d_HOUT[((size_t)tdst*BB + b)*(2*NH) + d*NH + u0];
            *reinterpret_cast<float4*>(ho)     = v0;
            *reinterpret_cast<float4*>(ho + 4) = v1;
        }

        // grid barrier (release/acquire via tid0)
        __syncthreads();
        if (tid == 0){
            __threadfence();
            atomicAdd(&d_bar, 1u);
            unsigned target = 128u*(unsigned)(t+1);
            volatile unsigned* vb = &d_bar;
            while (*vb < target) { __nanosleep(20); }
            __threadfence();
        }
        __syncthreads();
    }
}

// ---------------- masked softmax over T per (b,r) ----------------
__global__ void softmax_kernel(const int* __restrict__ len){
    int b = blockIdx.x / RR_, rr = blockIdx.x % RR_;
    int L = len[b];
    int tid = threadIdx.x;
    int t1 = tid + 256;
    float v0 = (tid < L) ? d_S2[((size_t)tid*BB + b)*RR_ + rr] : -1e30f;
    float v1 = (t1  < L) ? d_S2[((size_t)t1 *BB + b)*RR_ + rr] : -1e30f;
    __shared__ float red[256];
    red[tid] = fmaxf(v0, v1);
    __syncthreads();
    for (int s=128; s>0; s>>=1){ if (tid<s) red[tid] = fmaxf(red[tid], red[tid+s]); __syncthreads(); }
    float vmax = red[0];
    __syncthreads();
    float e0 = (tid < L) ? __expf(v0 - vmax) : 0.f;
    float e1 = (t1  < L) ? __expf(v1 - vmax) : 0.f;
    red[tid] = e0 + e1;
    __syncthreads();
    for (int s=128; s>0; s>>=1){ if (tid<s) red[tid] += red[tid+s]; __syncthreads(); }
    float inv = 1.f / red[0];
    size_t base = ((size_t)b*RR_ + rr)*TT;
    d_A[base + tid] = e0 * inv;
    d_A[base + t1 ] = e1 * inv;
}

// ---------------- M = A @ Hout  (2 h-values per thread, f32x2) ----------------
__global__ void mpool_kernel(){
    int b = blockIdx.y;
    int h = (blockIdx.x*256 + threadIdx.x)*2;  // even h in [0,1024)
    __shared__ __align__(16) float sa[RR_][66];
    ull acc[RR_];
    #pragma unroll
    for (int rr=0; rr<RR_; rr++) acc[rr] = 0ULL;
    for (int tc=0; tc<TT; tc+=64){
        for (int i = threadIdx.x; i < RR_*64; i += 256){
            int rr = i >> 6, tt = i & 63;
            sa[rr][tt] = d_A[((size_t)b*RR_ + rr)*TT + tc + tt];
        }
        __syncthreads();
        for (int tt=0; tt<64; tt++){
            float2 hv = *reinterpret_cast<const float2*>(
                &d_HOUT[((size_t)(tc+tt)*BB + b)*(2*NH) + h]);
            ull hv2 = pk(hv.x, hv.y);
            #pragma unroll
            for (int rr=0; rr<RR_; rr++)
                acc[rr] = fma2(pk2(sa[rr][tt]), hv2, acc[rr]);
        }
        __syncthreads();
    }
    #pragma unroll
    for (int rr=0; rr<RR_; rr++){
        float2 f2 = upk(acc[rr]);
        *reinterpret_cast<float2*>(&d_M[((size_t)b*RR_ + rr)*(2*NH) + h]) = f2;
    }
}

// ---------------- penalization ||AA^T - I||_F^2 ----------------
__global__ void aat_kernel(){
    int b = blockIdx.x, tid = threadIdx.x;
    float loc = 0.f;
    for (int p = tid; p < RR_*RR_; p += 256){
        int r = p / RR_, s = p % RR_;
        const float4* Ar = (const float4*)(d_A + ((size_t)b*RR_ + r)*TT);
        const float4* As = (const float4*)(d_A + ((size_t)b*RR_ + s)*TT);
        float dot = 0.f;
        for (int k=0; k<TT/4; k++){
            float4 x = Ar[k], y = As[k];
            dot += x.x*y.x + x.y*y.y + x.z*y.z + x.w*y.w;
        }
        float dd = dot - (r==s ? 1.f : 0.f);
        loc += dd*dd;
    }
    __shared__ float red[256];
    red[tid] = loc;
    __syncthreads();
    for (int s=128; s>0; s>>=1){ if (tid<s) red[tid] += red[tid+s]; __syncthreads(); }
    if (tid == 0) atomicAdd(&d_penal, red[0]);
}

// ---------------- split-K reduce + bias + relu ----------------
__global__ void rbias_relu(const float* __restrict__ bm){
    int idx = blockIdx.x*256 + threadIdx.x;
    if (idx >= BB*MLPH) return;
    int n = idx % MLPH;
    float s = 0.f;
    #pragma unroll
    for (int z=0; z<NZSPLIT; z++) s += d_SPL[(size_t)z*BB*MLPH + idx];
    d_RELU[idx] = fmaxf(s + bm[n], 0.f);
}

// ---------------- final decode + penal write ----------------
__global__ void decode_kernel(const float* __restrict__ Wd, const float* __restrict__ bd,
                              float* __restrict__ out, int out_size){
    int b = blockIdx.x, tid = threadIdx.x;
    float p[NCLS] = {0.f,0.f,0.f,0.f,0.f};
    for (int k = tid; k < MLPH; k += 256){
        float v = d_RELU[(size_t)b*MLPH + k];
        #pragma unroll
        for (int c=0; c<NCLS; c++) p[c] += v * Wd[(size_t)c*MLPH + k];
    }
    __shared__ float red[256];
    for (int c=0; c<NCLS; c++){
        red[tid] = p[c];
        __syncthreads();
        for (int s=128; s>0; s>>=1){ if (tid<s) red[tid] += red[tid+s]; __syncthreads(); }
        if (tid == 0) out[b*NCLS + c] = red[0] + bd[c];
        __syncthreads();
    }
    if (b == 0 && tid == 0 && out_size > BB*NCLS)
        out[BB*NCLS] = d_penal * (1.f/BB);
}

// ---------------- launch ----------------
extern "C" void kernel_launch(void* const* d_in, const int* in_sizes, int n_in,
                              void* d_out, int out_size){
    const int*   ids  = (const int*)  d_in[0];
    const int*   len  = (const int*)  d_in[1];
    const float* emb  = (const float*)d_in[2];
    const float* Wihf = (const float*)d_in[3];
    const float* Whhf = (const float*)d_in[4];
    const float* Wihb = (const float*)d_in[5];
    const float* Whhb = (const float*)d_in[6];
    const float* W1   = (const float*)d_in[7];
    const float* W2   = (const float*)d_in[8];
    const float* Wm   = (const float*)d_in[9];
    const float* bm   = (const float*)d_in[10];
    const float* Wd   = (const float*)d_in[11];
    const float* bd   = (const float*)d_in[12];
    float* out = (float*)d_out;

    void *pX, *pXGf, *pXGb, *pHOUT, *pS1, *pS2, *pM, *pSPL;
    cudaGetSymbolAddress(&pX,    d_X);
    cudaGetSymbolAddress(&pXGf,  d_XGf);
    cudaGetSymbolAddress(&pXGb,  d_XGb);
    cudaGetSymbolAddress(&pHOUT, d_HOUT);
    cudaGetSymbolAddress(&pS1,   d_S1);
    cudaGetSymbolAddress(&pS2,   d_S2);
    cudaGetSymbolAddress(&pM,    d_M);
    cudaGetSymbolAddress(&pSPL,  d_SPL);

    static int smem_set = 0;
    const int SMEM_LSTM = (32*WSTR + 64*68 + 32*65) * 4;  // 91776 B
    if (!smem_set){
        cudaFuncSetAttribute(lstm_persist, cudaFuncAttributeMaxDynamicSharedMemorySize, SMEM_LSTM);
        smem_set = 1;
    }

    init_zero<<<512,256>>>();
    embed_kernel<<<MT,128>>>(ids, len, emb);

    // xg = X @ W_ih^T, stored transposed [t][gate_row][b]
    dim3 gXG(G4/128, MT/64, 1);
    sgemm_tn<<<gXG,256>>>((const float*)pX, Wihf, (float*)pXGf, MT, G4, NI, NI, 2);
    sgemm_tn<<<gXG,256>>>((const float*)pX, Wihb, (float*)pXGb, MT, G4, NI, NI, 2);

    // persistent bidirectional recurrence (single launch, 512 steps)
    lstm_persist<<<128,256,SMEM_LSTM>>>(len, Whhf, Whhb);

    // attention scores
    dim3 gS1((DA_+127)/128, MT/64, 1);
    sgemm_tn<<<gS1,256>>>((const float*)pHOUT, W1, (float*)pS1, MT, DA_, 2*NH, 2*NH, 1);
    dim3 gS2(1, MT/64, 1);
    sgemm_tn<<<gS2,256>>>((const float*)pS1, W2, (float*)pS2, MT, RR_, DA_, DA_, 0);

    softmax_kernel<<<BB*RR_,256>>>(len);
    mpool_kernel<<<dim3(2,BB),256>>>();
    aat_kernel<<<BB,256>>>();

    // MLP: split-K GEMM + reduce/bias/relu
    dim3 gM((MLPH+127)/128, 1, NZSPLIT);
    sgemm_tn<<<gM,256>>>((const float*)pM, Wm, (float*)pSPL, BB, MLPH, KMLP, KMLP/NZSPLIT, 0);
    rbias_relu<<<(BB*MLPH+255)/256,256>>>(bm);

    decode_kernel<<<BB,256>>>(Wd, bd, out, out_size);
}

// round 14
// speedup vs baseline: 2.2824x; 1.4423x over previous
#include <cuda_runtime.h>
#include <cuda_bf16.h>
#include <math.h>

typedef unsigned long long ull;

// ---------------- sizes ----------------
#define BB   64
#define TT   512
#define NI   300
#define NH   512
#define G4   2048   // 4*NH
#define DA_  350
#define RR_  30
#define MLPH 2000
#define NCLS 5
#define MT   (BB*TT)      // 32768 rows (m = t*64+b)
#define KMLP (RR_*2*NH)   // 30720
#define NZSPLIT 16

// ---------------- scratch ----------------
__device__ float d_X   [(size_t)TT*BB*NI];        // [t][b][300]  (m = t*64+b)
__device__ float d_XGf [(size_t)TT*G4*BB];        // [t][gate_row][b]  (transposed!)
__device__ float d_XGb [(size_t)TT*G4*BB];
__device__ float d_HBUF[2*2*BB*NH];               // [dir][phase][b][512]
__device__ float d_HOUT[(size_t)TT*BB*2*NH];      // [t][b][1024]  (m = t*64+b)
__device__ float d_S1  [(size_t)MT*DA_];
__device__ float d_S2  [(size_t)MT*RR_];
__device__ float d_A   [(size_t)BB*RR_*TT];       // [b][r][t]
__device__ float d_M   [(size_t)BB*RR_*2*NH];     // [b][r][1024] == BM [64][30720]
__device__ float d_SPL [(size_t)NZSPLIT*BB*MLPH];
__device__ float d_RELU[(size_t)BB*MLPH];
__device__ float d_penal;
__device__ unsigned d_bar;

// ---------------- f32x2 helpers ----------------
__device__ __forceinline__ ull pk2(float x){
    ull r; asm("mov.b64 %0, {%1, %1};" : "=l"(r) : "f"(x)); return r;
}
__device__ __forceinline__ ull pk(float x, float y){
    ull r; asm("mov.b64 %0, {%1, %2};" : "=l"(r) : "f"(x), "f"(y)); return r;
}
__device__ __forceinline__ ull fma2(ull a, ull b, ull c){
    ull d; asm("fma.rn.f32x2 %0, %1, %2, %3;" : "=l"(d) : "l"(a), "l"(b), "l"(c)); return d;
}
__device__ __forceinline__ float2 upk(ull v){
    float2 f; asm("mov.b64 {%0, %1}, %2;" : "=f"(f.x), "=f"(f.y) : "l"(v)); return f;
}
__device__ __forceinline__ float sigm(float x){ return 1.f/(1.f+__expf(-x)); }

// ---------------- init ----------------
__global__ void init_zero(){
    int idx = blockIdx.x*256 + threadIdx.x;
    if (idx < 2*2*BB*NH) d_HBUF[idx] = 0.f;
    if (idx == 0){ d_penal = 0.f; d_bar = 0u; }
}

// ---------------- embedding + mask ----------------
__global__ void embed_kernel(const int* __restrict__ ids, const int* __restrict__ len,
                             const float* __restrict__ emb){
    int bid = blockIdx.x;          // = t*64 + b
    int t = bid >> 6, b = bid & 63;
    int tid = threadIdx.x;
    if (tid >= 75) return;         // 300 floats = 75 float4
    float4 v;
    if (t < len[b]) {
        int id = ids[b*TT + t];
        v = ((const float4*)(emb + (size_t)id*NI))[tid];
    } else v = make_float4(0.f,0.f,0.f,0.f);
    ((float4*)(d_X + (size_t)bid*NI))[tid] = v;
}

// ---------------- generic SGEMM: C[m][n] = dot(A[m,:K], B[n,:K]) ----------------
// BM=64, BN=128, BK=32, 256 threads, 4x8 thread tile via f32x2.
// epi: 0 = plain, 1 = tanh, 2 = transposed store C^T per 64-row block:
//      Cz[((m>>6)*N + n)*64 + (m&63)]   (requires full tiles: M%64==0, N%128==0)
__global__ void sgemm_tn(const float* __restrict__ A, const float* __restrict__ Bw,
                         float* __restrict__ C, int M, int N, int K,
                         int kSplitLen, int epi){
    __shared__ __align__(16) float smbuf[32*68 + 32*132];
    float* smA = smbuf;             // [32][68]
    float* smB = smbuf + 32*68;     // [32][132]
    int mBase = blockIdx.y * 64;
    int nBase = blockIdx.x * 128;
    int k0 = blockIdx.z * kSplitLen;
    int k1 = min(K, k0 + kSplitLen);
    float* Cz = C + (size_t)blockIdx.z * M * N;
    int tid = threadIdx.x;
    int tm = (tid >> 4) << 2;   // 0..60
    int tn = (tid & 15) << 3;   // 0..120
    ull acc[4][4];
    #pragma unroll
    for (int i=0;i<4;i++)
        #pragma unroll
        for (int j=0;j<4;j++) acc[i][j] = 0ULL;

    int kkA = tid & 31, rA = (tid >> 5) << 3;   // 8 rows / thread
    int kkB = tid & 31, rB = (tid >> 5) << 4;   // 16 rows / thread

    for (int kc = k0; kc < k1; kc += 32){
        #pragma unroll
        for (int i=0;i<8;i++){
            int m = mBase + rA + i; int k = kc + kkA;
            smA[kkA*68 + rA+i] = (m < M && k < k1) ? A[(size_t)m*K + k] : 0.f;
        }
        #pragma unroll
        for (int i=0;i<16;i++){
            int n = nBase + rB + i; int k = kc + kkB;
            smB[kkB*132 + rB+i] = (n < N && k < k1) ? Bw[(size_t)n*K + k] : 0.f;
        }
        __syncthreads();
        #pragma unroll
        for (int k=0;k<32;k++){
            float4 a4 = *reinterpret_cast<const float4*>(&smA[k*68 + tm]);
            ulonglong2 q0 = *reinterpret_cast<const ulonglong2*>(&smB[k*132 + tn]);
            ulonglong2 q1 = *reinterpret_cast<const ulonglong2*>(&smB[k*132 + tn+4]);
            ull ap0 = pk2(a4.x), ap1 = pk2(a4.y), ap2 = pk2(a4.z), ap3 = pk2(a4.w);
            acc[0][0]=fma2(ap0,q0.x,acc[0][0]); acc[0][1]=fma2(ap0,q0.y,acc[0][1]);
            acc[0][2]=fma2(ap0,q1.x,acc[0][2]); acc[0][3]=fma2(ap0,q1.y,acc[0][3]);
            acc[1][0]=fma2(ap1,q0.x,acc[1][0]); acc[1][1]=fma2(ap1,q0.y,acc[1][1]);
            acc[1][2]=fma2(ap1,q1.x,acc[1][2]); acc[1][3]=fma2(ap1,q1.y,acc[1][3]);
            acc[2][0]=fma2(ap2,q0.x,acc[2][0]); acc[2][1]=fma2(ap2,q0.y,acc[2][1]);
            acc[2][2]=fma2(ap2,q1.x,acc[2][2]); acc[2][3]=fma2(ap2,q1.y,acc[2][3]);
            acc[3][0]=fma2(ap3,q0.x,acc[3][0]); acc[3][1]=fma2(ap3,q0.y,acc[3][1]);
            acc[3][2]=fma2(ap3,q1.x,acc[3][2]); acc[3][3]=fma2(ap3,q1.y,acc[3][3]);
        }
        __syncthreads();
    }

    if (epi == 2){
        // transposed store via smem stage: Cs[n_local][m_local], stride 65
        float* Cs = smbuf;
        int myHalf = (tn >= 64) ? 1 : 0;
        #pragma unroll
        for (int half=0; half<2; half++){
            __syncthreads();
            if (half == myHalf){
                #pragma unroll
                for (int i=0;i<4;i++)
                    #pragma unroll
                    for (int j=0;j<4;j++){
                        float2 f2 = upk(acc[i][j]);
                        int nl = tn + 2*j - half*64;
                        Cs[nl*65 + tm+i]     = f2.x;
                        Cs[(nl+1)*65 + tm+i] = f2.y;
                    }
            }
            __syncthreads();
            int row = tid >> 2, part = tid & 3;
            size_t gbase = ((size_t)(mBase >> 6) * N + (nBase + half*64 + row)) * 64 + part*16;
            #pragma unroll
            for (int w=0; w<4; w++){
                float4 v;
                v.x = Cs[row*65 + part*16 + w*4 + 0];
                v.y = Cs[row*65 + part*16 + w*4 + 1];
                v.z = Cs[row*65 + part*16 + w*4 + 2];
                v.w = Cs[row*65 + part*16 + w*4 + 3];
                *reinterpret_cast<float4*>(Cz + gbase + w*4) = v;
            }
        }
        return;
    }

    #pragma unroll
    for (int i=0;i<4;i++){
        int m = mBase + tm + i;
        if (m >= M) continue;
        #pragma unroll
        for (int j=0;j<4;j++){
            float2 f2 = upk(acc[i][j]);
            int n = nBase + tn + 2*j;
            if (n < N){
                float v = f2.x; if (epi==1) v = tanhf(v);
                Cz[(size_t)m*N + n] = v;
            }
            if (n+1 < N){
                float v = f2.y; if (epi==1) v = tanhf(v);
                Cz[(size_t)m*N + n + 1] = v;
            }
        }
    }
}

// ---------------- persistent bidirectional LSTM (one launch, 512 steps) ----------------
// 128 blocks: dir = bid>>6, 8 hidden units per block. Warp = one unit.
// Thread = all 4 gates of one unit x 2 batches -> cell update entirely in regs.
// wsT[k][u][gate] in smem (one bcast LDS.128 per k), h via LDS.64.
__global__ void __launch_bounds__(256,1)
lstm_persist(const int* __restrict__ len,
             const float* __restrict__ Whhf,
             const float* __restrict__ Whhb){
    extern __shared__ __align__(16) float sm[];
    float* wsT = sm;                   // [512][8][4] = 16384 floats
    float* hs  = sm + 16384;           // [64][68]
    float* sh  = hs + 64*68;           // [8][64]

    int tid = threadIdx.x;
    int d  = blockIdx.x >> 6;
    int u0 = (blockIdx.x & 63) << 3;
    const float* W   = d ? Whhb : Whhf;
    const float* XGd = d ? d_XGb : d_XGf;   // [t][gate_row][b]

    // load W transposed: wsT[(k*8+u)*4+g] = W[(g*512 + u0+u)*512 + k]
    for (int rr = 0; rr < 32; rr++){
        int g = rr >> 3, u = rr & 7;
        int row = g*NH + u0 + u;
        for (int k = tid; k < NH; k += 256)
            wsT[(k*8 + u)*4 + g] = W[(size_t)row*NH + k];
    }

    int u  = tid >> 5;                 // unit within block (warp id)
    int bp = tid & 31;
    int b  = bp << 1;                  // batches b, b+1
    int cu = u0 + u;
    int lb0 = len[b], lb1 = len[b+1];

    float c0i=0.f, c0f=0.f;  // unused placeholder names avoided; cells:
    float cA = 0.f, cB = 0.f;          // cell state for (cu,b), (cu,b+1)
    (void)c0i; (void)c0f;
    int lw = (tid < 64) ? len[tid] : 0;

    int kk = tid & 63, bbase = (tid >> 6) << 4;   // hs chunk loader
    __syncthreads();

    float* HB = d_HBUF + (size_t)d*2*(BB*NH);

    for (int t = 0; t < TT; t++){
        const float* Hin = HB + (size_t)(t & 1)*(BB*NH);
        float*      Hnxt = HB + (size_t)((t+1) & 1)*(BB*NH);
        ull a0=0ULL, a1=0ULL, a2=0ULL, a3=0ULL;   // gates i,f,g,o (2 batches packed)

        // prefetch chunk 0
        float rbuf[16];
        #pragma unroll
        for (int i=0;i<16;i++)
            rbuf[i] = __ldcg(&Hin[(bbase+i)*NH + kk]);

        for (int kc = 0; kc < NH; kc += 64){
            __syncthreads();           // hs free
            #pragma unroll
            for (int q=0;q<4;q++){
                float4 v = make_float4(rbuf[4*q], rbuf[4*q+1], rbuf[4*q+2], rbuf[4*q+3]);
                *reinterpret_cast<float4*>(&hs[kk*68 + bbase + 4*q]) = v;
            }
            __syncthreads();           // hs ready
            if (kc + 64 < NH){
                #pragma unroll
                for (int i=0;i<16;i++)
                    rbuf[i] = __ldcg(&Hin[(bbase+i)*NH + kc + 64 + kk]);
            }
            const float* wp = wsT + ((size_t)kc*8 + u)*4;
            const float* hp = hs + b;
            #pragma unroll
            for (int k=0;k<64;k++){
                float4 w4 = *reinterpret_cast<const float4*>(wp);
                ull h2 = *reinterpret_cast<const ull*>(hp);
                a0 = fma2(pk2(w4.x), h2, a0);
                a1 = fma2(pk2(w4.y), h2, a1);
                a2 = fma2(pk2(w4.z), h2, a2);
                a3 = fma2(pk2(w4.w), h2, a3);
                wp += 32; hp += 68;
            }
        }

        // xg add (layout [t][gate_row][b], coalesced in b) + activations in regs
        int ts0 = (d && t < lb0) ? (lb0-1-t) : t;
        int ts1 = (d && t < lb1) ? (lb1-1-t) : t;
        float2 fi = upk(a0), ff = upk(a1), fg = upk(a2), fo = upk(a3);
        {
            size_t base0 = ((size_t)ts0*G4)*64 + b;
            size_t base1 = ((size_t)ts1*G4)*64 + (b+1);
            float gi0 = fi.x + __ldg(&XGd[base0 + (size_t)(0*NH+cu)*64]);
            float gf0 = ff.x + __ldg(&XGd[base0 + (size_t)(1*NH+cu)*64]);
            float gg0 = fg.x + __ldg(&XGd[base0 + (size_t)(2*NH+cu)*64]);
            float go0 = fo.x + __ldg(&XGd[base0 + (size_t)(3*NH+cu)*64]);
            float gi1 = fi.y + __ldg(&XGd[base1 + (size_t)(0*NH+cu)*64]);
            float gf1 = ff.y + __ldg(&XGd[base1 + (size_t)(1*NH+cu)*64]);
            float gg1 = fg.y + __ldg(&XGd[base1 + (size_t)(2*NH+cu)*64]);
            float go1 = fo.y + __ldg(&XGd[base1 + (size_t)(3*NH+cu)*64]);
            cA = sigm(gf0)*cA + sigm(gi0)*tanhf(gg0);
            cB = sigm(gf1)*cB + sigm(gi1)*tanhf(gg1);
            float h0 = sigm(go0)*tanhf(cA);
            float h1 = sigm(go1)*tanhf(cB);
            sh[u*64 + b]     = h0;
            sh[u*64 + b + 1] = h1;
        }
        __syncthreads();

        if (tid < 64){
            int bb = tid;
            float4 v0, v1;
            v0.x = sh[0*64+bb]; v0.y = sh[1*64+bb]; v0.z = sh[2*64+bb]; v0.w = sh[3*64+bb];
            v1.x = sh[4*64+bb]; v1.y = sh[5*64+bb]; v1.z = sh[6*64+bb]; v1.w = sh[7*64+bb];
            *reinterpret_cast<float4*>(&Hnxt[bb*NH + u0])     = v0;
            *reinterpret_cast<float4*>(&Hnxt[bb*NH + u0 + 4]) = v1;
            int tdst = (t < lw) ? (d ? (lw-1-t) : t) : t;
            float* ho = &d_HOUT[((size_t)tdst*BB + bb)*(2*NH) + d*NH + u0];
            *reinterpret_cast<float4*>(ho)     = v0;
            *reinterpret_cast<float4*>(ho + 4) = v1;
        }

        // grid barrier
        __syncthreads();
        if (tid == 0){
            __threadfence();
            atomicAdd(&d_bar, 1u);
            unsigned target = 128u*(unsigned)(t+1);
            volatile unsigned* vb = &d_bar;
            while (*vb < target) { __nanosleep(20); }
            __threadfence();
        }
        __syncthreads();
    }
}

// ---------------- masked softmax over T per (b,r) ----------------
__global__ void softmax_kernel(const int* __restrict__ len){
    int b = blockIdx.x / RR_, rr = blockIdx.x % RR_;
    int L = len[b];
    int tid = threadIdx.x;
    int t1 = tid + 256;
    float v0 = (tid < L) ? d_S2[((size_t)tid*BB + b)*RR_ + rr] : -1e30f;
    float v1 = (t1  < L) ? d_S2[((size_t)t1 *BB + b)*RR_ + rr] : -1e30f;
    __shared__ float red[256];
    red[tid] = fmaxf(v0, v1);
    __syncthreads();
    for (int s=128; s>0; s>>=1){ if (tid<s) red[tid] = fmaxf(red[tid], red[tid+s]); __syncthreads(); }
    float vmax = red[0];
    __syncthreads();
    float e0 = (tid < L) ? __expf(v0 - vmax) : 0.f;
    float e1 = (t1  < L) ? __expf(v1 - vmax) : 0.f;
    red[tid] = e0 + e1;
    __syncthreads();
    for (int s=128; s>0; s>>=1){ if (tid<s) red[tid] += red[tid+s]; __syncthreads(); }
    float inv = 1.f / red[0];
    size_t base = ((size_t)b*RR_ + rr)*TT;
    d_A[base + tid] = e0 * inv;
    d_A[base + t1 ] = e1 * inv;
}

// ---------------- M = A @ Hout  (2 h-values per thread, f32x2) ----------------
__global__ void mpool_kernel(){
    int b = blockIdx.y;
    int h = (blockIdx.x*256 + threadIdx.x)*2;  // even h in [0,1024)
    __shared__ __align__(16) float sa[RR_][66];
    ull acc[RR_];
    #pragma unroll
    for (int rr=0; rr<RR_; rr++) acc[rr] = 0ULL;
    for (int tc=0; tc<TT; tc+=64){
        for (int i = threadIdx.x; i < RR_*64; i += 256){
            int rr = i >> 6, tt = i & 63;
            sa[rr][tt] = d_A[((size_t)b*RR_ + rr)*TT + tc + tt];
        }
        __syncthreads();
        for (int tt=0; tt<64; tt++){
            float2 hv = *reinterpret_cast<const float2*>(
                &d_HOUT[((size_t)(tc+tt)*BB + b)*(2*NH) + h]);
            ull hv2 = pk(hv.x, hv.y);
            #pragma unroll
            for (int rr=0; rr<RR_; rr++)
                acc[rr] = fma2(pk2(sa[rr][tt]), hv2, acc[rr]);
        }
        __syncthreads();
    }
    #pragma unroll
    for (int rr=0; rr<RR_; rr++){
        float2 f2 = upk(acc[rr]);
        *reinterpret_cast<float2*>(&d_M[((size_t)b*RR_ + rr)*(2*NH) + h]) = f2;
    }
}

// ---------------- penalization ||AA^T - I||_F^2 ----------------
__global__ void aat_kernel(){
    int b = blockIdx.x, tid = threadIdx.x;
    float loc = 0.f;
    for (int p = tid; p < RR_*RR_; p += 256){
        int r = p / RR_, s = p % RR_;
        const float4* Ar = (const float4*)(d_A + ((size_t)b*RR_ + r)*TT);
        const float4* As = (const float4*)(d_A + ((size_t)b*RR_ + s)*TT);
        float dot = 0.f;
        for (int k=0; k<TT/4; k++){
            float4 x = Ar[k], y = As[k];
            dot += x.x*y.x + x.y*y.y + x.z*y.z + x.w*y.w;
        }
        float dd = dot - (r==s ? 1.f : 0.f);
        loc += dd*dd;
    }
    __shared__ float red[256];
    red[tid] = loc;
    __syncthreads();
    for (int s=128; s>0; s>>=1){ if (tid<s) red[tid] += red[tid+s]; __syncthreads(); }
    if (tid == 0) atomicAdd(&d_penal, red[0]);
}

// ---------------- split-K reduce + bias + relu ----------------
__global__ void rbias_relu(const float* __restrict__ bm){
    int idx = blockIdx.x*256 + threadIdx.x;
    if (idx >= BB*MLPH) return;
    int n = idx % MLPH;
    float s = 0.f;
    #pragma unroll
    for (int z=0; z<NZSPLIT; z++) s += d_SPL[(size_t)z*BB*MLPH + idx];
    d_RELU[idx] = fmaxf(s + bm[n], 0.f);
}

// ---------------- final decode + penal write ----------------
__global__ void decode_kernel(const float* __restrict__ Wd, const float* __restrict__ bd,
                              float* __restrict__ out, int out_size){
    int b = blockIdx.x, tid = threadIdx.x;
    float p[NCLS] = {0.f,0.f,0.f,0.f,0.f};
    for (int k = tid; k < MLPH; k += 256){
        float v = d_RELU[(size_t)b*MLPH + k];
        #pragma unroll
        for (int c=0; c<NCLS; c++) p[c] += v * Wd[(size_t)c*MLPH + k];
    }
    __shared__ float red[256];
    for (int c=0; c<NCLS; c++){
        red[tid] = p[c];
        __syncthreads();
        for (int s=128; s>0; s>>=1){ if (tid<s) red[tid] += red[tid+s]; __syncthreads(); }
        if (tid == 0) out[b*NCLS + c] = red[0] + bd[c];
        __syncthreads();
    }
    if (b == 0 && tid == 0 && out_size > BB*NCLS)
        out[BB*NCLS] = d_penal * (1.f/BB);
}

// ---------------- launch ----------------
extern "C" void kernel_launch(void* const* d_in, const int* in_sizes, int n_in,
                              void* d_out, int out_size){
    const int*   ids  = (const int*)  d_in[0];
    const int*   len  = (const int*)  d_in[1];
    const float* emb  = (const float*)d_in[2];
    const float* Wihf = (const float*)d_in[3];
    const float* Whhf = (const float*)d_in[4];
    const float* Wihb = (const float*)d_in[5];
    const float* Whhb = (const float*)d_in[6];
    const float* W1   = (const float*)d_in[7];
    const float* W2   = (const float*)d_in[8];
    const float* Wm   = (const float*)d_in[9];
    const float* bm   = (const float*)d_in[10];
    const float* Wd   = (const float*)d_in[11];
    const float* bd   = (const float*)d_in[12];
    float* out = (float*)d_out;

    void *pX, *pXGf, *pXGb, *pHOUT, *pS1, *pS2, *pM, *pSPL;
    cudaGetSymbolAddress(&pX,    d_X);
    cudaGetSymbolAddress(&pXGf,  d_XGf);
    cudaGetSymbolAddress(&pXGb,  d_XGb);
    cudaGetSymbolAddress(&pHOUT, d_HOUT);
    cudaGetSymbolAddress(&pS1,   d_S1);
    cudaGetSymbolAddress(&pS2,   d_S2);
    cudaGetSymbolAddress(&pM,    d_M);
    cudaGetSymbolAddress(&pSPL,  d_SPL);

    static int smem_set = 0;
    const int SMEM_LSTM = (16384 + 64*68 + 8*64) * 4;  // 84992 B
    if (!smem_set){
        cudaFuncSetAttribute(lstm_persist, cudaFuncAttributeMaxDynamicSharedMemorySize, SMEM_LSTM);
        smem_set = 1;
    }

    init_zero<<<512,256>>>();
    embed_kernel<<<MT,128>>>(ids, len, emb);

    // xg = X @ W_ih^T, stored transposed [t][gate_row][b]
    dim3 gXG(G4/128, MT/64, 1);
    sgemm_tn<<<gXG,256>>>((const float*)pX, Wihf, (float*)pXGf, MT, G4, NI, NI, 2);
    sgemm_tn<<<gXG,256>>>((const float*)pX, Wihb, (float*)pXGb, MT, G4, NI, NI, 2);

    // persistent bidirectional recurrence (single launch, 512 steps)
    lstm_persist<<<128,256,SMEM_LSTM>>>(len, Whhf, Whhb);

    // attention scores
    dim3 gS1((DA_+127)/128, MT/64, 1);
    sgemm_tn<<<gS1,256>>>((const float*)pHOUT, W1, (float*)pS1, MT, DA_, 2*NH, 2*NH, 1);
    dim3 gS2(1, MT/64, 1);
    sgemm_tn<<<gS2,256>>>((const float*)pS1, W2, (float*)pS2, MT, RR_, DA_, DA_, 0);

    softmax_kernel<<<BB*RR_,256>>>(len);
    mpool_kernel<<<dim3(2,BB),256>>>();
    aat_kernel<<<BB,256>>>();

    // MLP: split-K GEMM + reduce/bias/relu
    dim3 gM((MLPH+127)/128, 1, NZSPLIT);
    sgemm_tn<<<gM,256>>>((const float*)pM, Wm, (float*)pSPL, BB, MLPH, KMLP, KMLP/NZSPLIT, 0);
    rbias_relu<<<(BB*MLPH+255)/256,256>>>(bm);

    decode_kernel<<<BB,256>>>(Wd, bd, out, out_size);
}